// round 4
// baseline (speedup 1.0000x reference)
#include <cuda_runtime.h>
#include <cstdint>

#define NN 100000
#define NP 100032          // padded to multiple of 64 for GEMM tiles
#define NE 1600000

// ---------------- scratch (device globals; no allocations allowed) ----------
__device__ __align__(16) float g_deg [NN];
__device__ __align__(16) float g_acc0[NN * 48];
__device__ __align__(16) float g_hin [NP * 192];  // [h(96) | mean_neigh_h(96)]
__device__ __align__(16) float g_acc1[NN * 96];
__device__ __align__(16) float g_h1  [NP * 128];
__device__ __align__(16) float g_q   [NP * 64];   // h1 @ W2s
__device__ __align__(16) float g_p2  [NP * 64];   // h1 @ W2n (pushed before aggregation)
__device__ __align__(16) float g_acc2[NN * 64];

// 16B vector reduction to global (sm_90+)
__device__ __forceinline__ void red_add_v4(float* p, float4 v) {
    asm volatile("red.global.add.v4.f32 [%0], {%1, %2, %3, %4};"
                 :: "l"(p), "f"(v.x), "f"(v.y), "f"(v.z), "f"(v.w) : "memory");
}

// tf32 round (rna) -> bit pattern in uint
__device__ __forceinline__ unsigned to_tf32(float x) {
    unsigned u;
    asm("cvt.rna.tf32.f32 %0, %1;" : "=r"(u) : "f"(x));
    return u;
}

// m16n8k8 tf32 mma, D += A*B (acc in place)
__device__ __forceinline__ void mma_tf32(float* c, const unsigned* a,
                                         unsigned b0, unsigned b1) {
    asm volatile("mma.sync.aligned.m16n8k8.row.col.f32.tf32.tf32.f32 "
                 "{%0,%1,%2,%3}, {%4,%5,%6,%7}, {%8,%9}, {%0,%1,%2,%3};"
                 : "+f"(c[0]), "+f"(c[1]), "+f"(c[2]), "+f"(c[3])
                 : "r"(a[0]), "r"(a[1]), "r"(a[2]), "r"(a[3]), "r"(b0), "r"(b1));
}

// ---------------- K0: zero accumulators -------------------------------------
__global__ void k_zero() {
    int idx = blockIdx.x * blockDim.x + threadIdx.x;
    int stride = gridDim.x * blockDim.x;
    float4 z = make_float4(0.f, 0.f, 0.f, 0.f);
    for (int i = idx; i < NN * 48 / 4; i += stride) ((float4*)g_acc0)[i] = z;
    for (int i = idx; i < NN * 96 / 4; i += stride) ((float4*)g_acc1)[i] = z;
    for (int i = idx; i < NN * 64 / 4; i += stride) ((float4*)g_acc2)[i] = z;
    for (int i = idx; i < NN / 4;      i += stride) ((float4*)g_deg)[i]  = z;
}

// ---------------- K1: edge encoder + u_mul_e message + scatter ---------------
__global__ void __launch_bounds__(128) k_edge0(
    const float* __restrict__ efeat, const float* __restrict__ nfeat,
    const int* __restrict__ src, const int* __restrict__ dst,
    const float* __restrict__ We, const float* __restrict__ be)
{
    __shared__ float sW[32 * 48];
    __shared__ float sB[48];
    for (int i = threadIdx.x; i < 32 * 48; i += 128) sW[i] = We[i];
    if (threadIdx.x < 48) sB[threadIdx.x] = be[threadIdx.x];
    __syncthreads();

    int e = blockIdx.x * 128 + threadIdx.x;
    if (e >= NE) return;

    int s = src[e], d = dst[e];
    float ef[32];
    const float4* efp = (const float4*)(efeat + (size_t)e * 32);
#pragma unroll
    for (int k = 0; k < 8; k++) {
        float4 t = efp[k];
        ef[4*k] = t.x; ef[4*k+1] = t.y; ef[4*k+2] = t.z; ef[4*k+3] = t.w;
    }
    atomicAdd(&g_deg[d], 1.0f);

    const float4* nf = (const float4*)(nfeat + (size_t)s * 48);
    float* out0 = g_acc0 + (size_t)d * 48;
    float* out1 = g_acc1 + (size_t)d * 96;

#pragma unroll
    for (int jb = 0; jb < 12; jb++) {
        float4 a = ((const float4*)sB)[jb];
#pragma unroll
        for (int k = 0; k < 32; k++) {
            float4 w = *(const float4*)(sW + k * 48 + jb * 4);
            a.x = fmaf(ef[k], w.x, a.x);
            a.y = fmaf(ef[k], w.y, a.y);
            a.z = fmaf(ef[k], w.z, a.z);
            a.w = fmaf(ef[k], w.w, a.w);
        }
        float4 nv = nf[jb];
        a.x = fmaxf(a.x, 0.f) * nv.x;
        a.y = fmaxf(a.y, 0.f) * nv.y;
        a.z = fmaxf(a.z, 0.f) * nv.z;
        a.w = fmaxf(a.w, 0.f) * nv.w;
        red_add_v4(out0 + jb * 4, a);
        red_add_v4(out1 + jb * 4, nv);
    }
}

// ---------------- K2: g_hin[:, 0:96] = [nfeat | acc0/deg] --------------------
__global__ void k_build_h(const float* __restrict__ nfeat) {
    int idx = blockIdx.x * blockDim.x + threadIdx.x;
    if (idx >= NN * 24) return;
    int n = idx / 24, c = idx - n * 24;
    float4 v;
    if (c < 12) {
        v = ((const float4*)nfeat)[(size_t)n * 12 + c];
    } else {
        float inv = 1.0f / fmaxf(g_deg[n], 1.0f);
        float4 t = ((const float4*)g_acc0)[(size_t)n * 12 + (c - 12)];
        v.x = t.x * inv; v.y = t.y * inv; v.z = t.z * inv; v.w = t.w * inv;
    }
    ((float4*)(g_hin + (size_t)n * 192))[c] = v;
}

// ---------------- K3: gather h_neigh0[src] -> acc1[dst][48:96] ---------------
__global__ void k_edge1(const int* __restrict__ src, const int* __restrict__ dst) {
    int idx = blockIdx.x * blockDim.x + threadIdx.x;
    if (idx >= NE * 12) return;
    int e = idx / 12, c = idx - e * 12;
    int s = src[e], d = dst[e];
    float4 v = ((const float4*)(g_hin + (size_t)s * 192 + 48))[c];
    red_add_v4(g_acc1 + (size_t)d * 96 + 48 + c * 4, v);
}

// ---------------- K4: g_hin[:, 96:192] = acc1/deg ----------------------------
__global__ void k_norm1() {
    int idx = blockIdx.x * blockDim.x + threadIdx.x;
    if (idx >= NN * 24) return;
    int n = idx / 24, c = idx - n * 24;
    float inv = 1.0f / fmaxf(g_deg[n], 1.0f);
    float4 t = ((const float4*)g_acc1)[(size_t)n * 24 + c];
    float4 v;
    v.x = t.x * inv; v.y = t.y * inv; v.z = t.z * inv; v.w = t.w * inv;
    ((float4*)(g_hin + (size_t)n * 192 + 96))[c] = v;
}

// ======================= tf32 tensor-core GEMMs =============================
// Tile: 64 nodes x 128 cols per block, K-chunks of 16.
// 8 warps: warp (w&3) -> 16-node row band, (w>>2) -> 64-col half.
// 3-term compensation: xh@Wh + xl@Wh + xh@Wl into one fp32 accumulator.
#define XPAD 17
#define WPAD 132

// ---------------- K5: h1 = relu(g_hin @ [W1s;W1n] + b1) ----------------------
__global__ void __launch_bounds__(256) k_gemm1(
    const float* __restrict__ W1s, const float* __restrict__ W1n,
    const float* __restrict__ b1)
{
    __shared__ float sXh[64 * XPAD], sXl[64 * XPAD];
    __shared__ float sWh[16 * WPAD], sWl[16 * WPAD];
    __shared__ float sB[128];
    int tid = threadIdx.x;
    int warp = tid >> 5, lane = tid & 31;
    int g = lane >> 2, t = lane & 3;
    int mrow = (warp & 3) * 16;
    int nhalf = (warp >> 2) * 64;
    if (tid < 128) sB[tid] = b1[tid];

    int nb = blockIdx.x * 64;
    float acc[8][4];
#pragma unroll
    for (int i = 0; i < 8; i++)
#pragma unroll
        for (int j = 0; j < 4; j++) acc[i][j] = 0.f;

    for (int kc = 0; kc < 12; kc++) {
        __syncthreads();
        {   // X chunk: 64 nodes x 16 k
            int n = tid >> 2, kq = tid & 3;
            float4 x = *(const float4*)(g_hin + (size_t)(nb + n) * 192 + kc * 16 + kq * 4);
            float xs[4] = {x.x, x.y, x.z, x.w};
#pragma unroll
            for (int j = 0; j < 4; j++) {
                float hi = __uint_as_float(to_tf32(xs[j]));
                float lo = __uint_as_float(to_tf32(xs[j] - hi));
                sXh[n * XPAD + kq * 4 + j] = hi;
                sXl[n * XPAD + kq * 4 + j] = lo;
            }
        }
        // W chunk: 16 k x 128 c
        for (int i = tid; i < 512; i += 256) {
            int k = i >> 5, c4 = i & 31;
            int gk = kc * 16 + k;
            float4 w = (gk < 96) ? *(const float4*)(W1s + gk * 128 + c4 * 4)
                                 : *(const float4*)(W1n + (gk - 96) * 128 + c4 * 4);
            float ws[4] = {w.x, w.y, w.z, w.w};
#pragma unroll
            for (int j = 0; j < 4; j++) {
                float hi = __uint_as_float(to_tf32(ws[j]));
                float lo = __uint_as_float(to_tf32(ws[j] - hi));
                sWh[k * WPAD + c4 * 4 + j] = hi;
                sWl[k * WPAD + c4 * 4 + j] = lo;
            }
        }
        __syncthreads();

#pragma unroll
        for (int ks = 0; ks < 16; ks += 8) {
            unsigned ah[4], al[4];
            int r0 = (mrow + g) * XPAD, r1 = (mrow + g + 8) * XPAD;
            ah[0] = __float_as_uint(sXh[r0 + ks + t]);
            ah[1] = __float_as_uint(sXh[r1 + ks + t]);
            ah[2] = __float_as_uint(sXh[r0 + ks + t + 4]);
            ah[3] = __float_as_uint(sXh[r1 + ks + t + 4]);
            al[0] = __float_as_uint(sXl[r0 + ks + t]);
            al[1] = __float_as_uint(sXl[r1 + ks + t]);
            al[2] = __float_as_uint(sXl[r0 + ks + t + 4]);
            al[3] = __float_as_uint(sXl[r1 + ks + t + 4]);
#pragma unroll
            for (int nc = 0; nc < 8; nc++) {
                int ncol = nhalf + nc * 8 + g;
                unsigned bh0 = __float_as_uint(sWh[(ks + t) * WPAD + ncol]);
                unsigned bh1 = __float_as_uint(sWh[(ks + t + 4) * WPAD + ncol]);
                unsigned bl0 = __float_as_uint(sWl[(ks + t) * WPAD + ncol]);
                unsigned bl1 = __float_as_uint(sWl[(ks + t + 4) * WPAD + ncol]);
                mma_tf32(acc[nc], ah, bh0, bh1);
                mma_tf32(acc[nc], al, bh0, bh1);
                mma_tf32(acc[nc], ah, bl0, bl1);
            }
        }
    }
    // epilogue: bias + relu
#pragma unroll
    for (int nc = 0; nc < 8; nc++) {
        int col = nhalf + nc * 8 + 2 * t;
        float b0 = sB[col], b1v = sB[col + 1];
        int row0 = nb + mrow + g, row1 = row0 + 8;
        float2 v0 = make_float2(fmaxf(acc[nc][0] + b0, 0.f), fmaxf(acc[nc][1] + b1v, 0.f));
        float2 v1 = make_float2(fmaxf(acc[nc][2] + b0, 0.f), fmaxf(acc[nc][3] + b1v, 0.f));
        *(float2*)(g_h1 + (size_t)row0 * 128 + col) = v0;
        *(float2*)(g_h1 + (size_t)row1 * 128 + col) = v1;
    }
}

// ---------------- K6: q = h1@W2s (cols 0..63), p2 = h1@W2n (cols 64..127) ----
__global__ void __launch_bounds__(256) k_gemm2(
    const float* __restrict__ W2s, const float* __restrict__ W2n)
{
    __shared__ float sXh[64 * XPAD], sXl[64 * XPAD];
    __shared__ float sWh[16 * WPAD], sWl[16 * WPAD];
    int tid = threadIdx.x;
    int warp = tid >> 5, lane = tid & 31;
    int g = lane >> 2, t = lane & 3;
    int mrow = (warp & 3) * 16;
    int nhalf = (warp >> 2) * 64;

    int nb = blockIdx.x * 64;
    float acc[8][4];
#pragma unroll
    for (int i = 0; i < 8; i++)
#pragma unroll
        for (int j = 0; j < 4; j++) acc[i][j] = 0.f;

    for (int kc = 0; kc < 8; kc++) {
        __syncthreads();
        {   // X chunk from g_h1
            int n = tid >> 2, kq = tid & 3;
            float4 x = *(const float4*)(g_h1 + (size_t)(nb + n) * 128 + kc * 16 + kq * 4);
            float xs[4] = {x.x, x.y, x.z, x.w};
#pragma unroll
            for (int j = 0; j < 4; j++) {
                float hi = __uint_as_float(to_tf32(xs[j]));
                float lo = __uint_as_float(to_tf32(xs[j] - hi));
                sXh[n * XPAD + kq * 4 + j] = hi;
                sXl[n * XPAD + kq * 4 + j] = lo;
            }
        }
        // W chunk: cols 0..63 = W2s, 64..127 = W2n
        for (int i = tid; i < 512; i += 256) {
            int k = i >> 5, c4 = i & 31;
            int gk = kc * 16 + k;
            float4 w = (c4 < 16) ? *(const float4*)(W2s + gk * 64 + c4 * 4)
                                 : *(const float4*)(W2n + gk * 64 + (c4 - 16) * 4);
            float ws[4] = {w.x, w.y, w.z, w.w};
#pragma unroll
            for (int j = 0; j < 4; j++) {
                float hi = __uint_as_float(to_tf32(ws[j]));
                float lo = __uint_as_float(to_tf32(ws[j] - hi));
                sWh[k * WPAD + c4 * 4 + j] = hi;
                sWl[k * WPAD + c4 * 4 + j] = lo;
            }
        }
        __syncthreads();

#pragma unroll
        for (int ks = 0; ks < 16; ks += 8) {
            unsigned ah[4], al[4];
            int r0 = (mrow + g) * XPAD, r1 = (mrow + g + 8) * XPAD;
            ah[0] = __float_as_uint(sXh[r0 + ks + t]);
            ah[1] = __float_as_uint(sXh[r1 + ks + t]);
            ah[2] = __float_as_uint(sXh[r0 + ks + t + 4]);
            ah[3] = __float_as_uint(sXh[r1 + ks + t + 4]);
            al[0] = __float_as_uint(sXl[r0 + ks + t]);
            al[1] = __float_as_uint(sXl[r1 + ks + t]);
            al[2] = __float_as_uint(sXl[r0 + ks + t + 4]);
            al[3] = __float_as_uint(sXl[r1 + ks + t + 4]);
#pragma unroll
            for (int nc = 0; nc < 8; nc++) {
                int ncol = nhalf + nc * 8 + g;
                unsigned bh0 = __float_as_uint(sWh[(ks + t) * WPAD + ncol]);
                unsigned bh1 = __float_as_uint(sWh[(ks + t + 4) * WPAD + ncol]);
                unsigned bl0 = __float_as_uint(sWl[(ks + t) * WPAD + ncol]);
                unsigned bl1 = __float_as_uint(sWl[(ks + t + 4) * WPAD + ncol]);
                mma_tf32(acc[nc], ah, bh0, bh1);
                mma_tf32(acc[nc], al, bh0, bh1);
                mma_tf32(acc[nc], ah, bl0, bl1);
            }
        }
    }
    // epilogue: route col<64 -> g_q, col>=64 -> g_p2 (nhalf decides whole warp)
    float* dstA = (nhalf == 0) ? g_q : g_p2;
#pragma unroll
    for (int nc = 0; nc < 8; nc++) {
        int col = nc * 8 + 2 * t;       // 0..63 within the chosen array
        int row0 = nb + mrow + g, row1 = row0 + 8;
        float2 v0 = make_float2(acc[nc][0], acc[nc][1]);
        float2 v1 = make_float2(acc[nc][2], acc[nc][3]);
        *(float2*)(dstA + (size_t)row0 * 64 + col) = v0;
        *(float2*)(dstA + (size_t)row1 * 64 + col) = v1;
    }
}

// ---------------- K7: gather p2[src] -> acc2[dst]  (64 floats = 16 chunks) ---
__global__ void k_edge2(const int* __restrict__ src, const int* __restrict__ dst) {
    int idx = blockIdx.x * blockDim.x + threadIdx.x;
    if (idx >= NE * 16) return;
    int e = idx >> 4, c = idx & 15;
    int s = src[e], d = dst[e];
    float4 v = ((const float4*)g_p2)[(size_t)s * 16 + c];
    red_add_v4(g_acc2 + (size_t)d * 64 + c * 4, v);
}

// ---------------- K8: out = q + acc2/deg + b2 --------------------------------
__global__ void k_final(const float* __restrict__ b2, float* __restrict__ outp) {
    int idx = blockIdx.x * blockDim.x + threadIdx.x;
    if (idx >= NN * 16) return;
    int n = idx >> 4, c = idx & 15;
    float inv = 1.0f / fmaxf(g_deg[n], 1.0f);
    float4 q  = ((const float4*)g_q)[(size_t)n * 16 + c];
    float4 a  = ((const float4*)g_acc2)[(size_t)n * 16 + c];
    float4 bb = ((const float4*)b2)[c];
    float4 r;
    r.x = q.x + a.x * inv + bb.x;
    r.y = q.y + a.y * inv + bb.y;
    r.z = q.z + a.z * inv + bb.z;
    r.w = q.w + a.w * inv + bb.w;
    ((float4*)outp)[idx] = r;
}

// ---------------- launch -----------------------------------------------------
extern "C" void kernel_launch(void* const* d_in, const int* in_sizes, int n_in,
                              void* d_out, int out_size)
{
    const float* nfeat = (const float*)d_in[0];
    const float* efeat = (const float*)d_in[1];
    const int*   src   = (const int*)  d_in[2];
    const int*   dst   = (const int*)  d_in[3];
    const float* We    = (const float*)d_in[4];
    const float* be    = (const float*)d_in[5];
    const float* W1s   = (const float*)d_in[6];
    const float* W1n   = (const float*)d_in[7];
    const float* b1    = (const float*)d_in[8];
    const float* W2s   = (const float*)d_in[9];
    const float* W2n   = (const float*)d_in[10];
    const float* b2    = (const float*)d_in[11];
    float* out = (float*)d_out;

    k_zero<<<2048, 256>>>();
    k_edge0<<<NE / 128, 128>>>(efeat, nfeat, src, dst, We, be);
    k_build_h<<<(NN * 24 + 255) / 256, 256>>>(nfeat);
    k_edge1<<<(NE * 12 + 255) / 256, 256>>>(src, dst);
    k_norm1<<<(NN * 24 + 255) / 256, 256>>>();
    k_gemm1<<<NP / 64, 256>>>(W1s, W1n, b1);
    k_gemm2<<<NP / 64, 256>>>(W2s, W2n);
    k_edge2<<<(NE * 16 + 255) / 256, 256>>>(src, dst);
    k_final<<<(NN * 16 + 255) / 256, 256>>>(b2, out);
}